// round 16
// baseline (speedup 1.0000x reference)
#include <cuda_runtime.h>
#include <cuda_bf16.h>

typedef unsigned long long ULL;

#define HW 784
#define NPIX 3136

// ---------------------------------------------------------------------------
// accd layout (doubles): ds_sum@0, ds_ss@256, bn2_sum@512, bn2_ss@576,
// bn3_sum@640, bn3_ss@896, bn1_sum@1152, bn1_ss@1216.
// KL partial slots: kp_*[t*40 + lb]  (blocks per tensor: 32/8/36/16).
// ---------------------------------------------------------------------------
struct __align__(16) Scratch {
    float f_ds[32768], f_c1[8192], f_c2[36864], f_c3[16384];
    float kp_ef[160], kp_el[160], kp_spl[160];
    double accd[1280];
    float buf_ds[802816], buf_c3[802816];
    float buf_c1[200704], buf_peg[200704], buf_c2[200704];
};
__device__ Scratch g_s;

// ---------------- helpers --------------------------------------------------
__device__ __forceinline__ ULL addf2(ULL a, ULL b) {
    ULL r; asm("add.rn.f32x2 %0,%1,%2;" : "=l"(r) : "l"(a), "l"(b)); return r;
}
__device__ __forceinline__ ULL pack2(float v) {
    ULL r; unsigned u = __float_as_uint(v);
    asm("mov.b64 %0,{%1,%1};" : "=l"(r) : "r"(u)); return r;
}
__device__ __forceinline__ ULL packAB(float a, float b) {
    return ((ULL)__float_as_uint(b) << 32) | (ULL)__float_as_uint(a);
}
#define ABS2_MASK 0x7FFFFFFF7FFFFFFFULL

__device__ __forceinline__ float blk_sum(float v) {
    __shared__ float red[8];
    #pragma unroll
    for (int o = 16; o > 0; o >>= 1) v += __shfl_xor_sync(0xffffffffu, v, o);
    int w = threadIdx.x >> 5, l = threadIdx.x & 31;
    if (l == 0) red[w] = v;
    __syncthreads();
    if (w == 0) {
        float s = (l < 8) ? red[l] : 0.f;
        #pragma unroll
        for (int o = 4; o > 0; o >>= 1) s += __shfl_xor_sync(0xffffffffu, s, o);
        if (l == 0) red[0] = s;
    }
    __syncthreads();
    float r = red[0]; __syncthreads();
    return r;
}
__device__ __forceinline__ void blk_minmax(float mn, float mx, float* omn, float* omx) {
    __shared__ float rmn[8], rmx[8];
    #pragma unroll
    for (int o = 16; o > 0; o >>= 1) {
        mn = fminf(mn, __shfl_xor_sync(0xffffffffu, mn, o));
        mx = fmaxf(mx, __shfl_xor_sync(0xffffffffu, mx, o));
    }
    int w = threadIdx.x >> 5, l = threadIdx.x & 31;
    if (l == 0) { rmn[w] = mn; rmx[w] = mx; }
    __syncthreads();
    if (w == 0) {
        float a = (l < 8) ? rmn[l] : 3.4e38f;
        float b = (l < 8) ? rmx[l] : -3.4e38f;
        #pragma unroll
        for (int o = 4; o > 0; o >>= 1) {
            a = fminf(a, __shfl_xor_sync(0xffffffffu, a, o));
            b = fmaxf(b, __shfl_xor_sync(0xffffffffu, b, o));
        }
        if (l == 0) { rmn[0] = a; rmx[0] = b; }
    }
    __syncthreads();
    *omn = rmn[0]; *omx = rmx[0];
    __syncthreads();
}

// ---------------- recon: zero accd + per-tensor minmax + recon + KL parts --
__global__ void __launch_bounds__(256) recon_kernel(
    const float* __restrict__ w0, const float* __restrict__ w1,
    const float* __restrict__ w2, const float* __restrict__ w3,
    const float* __restrict__ a0, const float* __restrict__ a1,
    const float* __restrict__ a2, const float* __restrict__ a3,
    const float* __restrict__ l0, const float* __restrict__ l1,
    const float* __restrict__ l2, const float* __restrict__ l3)
{
    int bid = blockIdx.x, tid = threadIdx.x;
    if (bid == 0) {
        #pragma unroll
        for (int i = 0; i < 5; ++i) g_s.accd[i * 256 + tid] = 0.0;
    }
    int t, lb;
    if (bid < 32)      { t = 0; lb = bid; }
    else if (bid < 40) { t = 1; lb = bid - 32; }
    else if (bid < 76) { t = 2; lb = bid - 40; }
    else               { t = 3; lb = bid - 76; }
    const float *w, *aff, *lap; float* f; int n4;
    if (t == 0)      { w = w0; aff = a0; lap = l0; f = g_s.f_ds; n4 = 8192; }
    else if (t == 1) { w = w1; aff = a1; lap = l1; f = g_s.f_c1; n4 = 2048; }
    else if (t == 2) { w = w2; aff = a2; lap = l2; f = g_s.f_c2; n4 = 9216; }
    else             { w = w3; aff = a3; lap = l3; f = g_s.f_c3; n4 = 4096; }

    float mn = 3.4e38f, mx = -3.4e38f;
    for (int i = tid; i < n4; i += 256) {
        float4 v = ((const float4*)w)[i];
        mn = fminf(mn, fminf(fminf(v.x, v.y), fminf(v.z, v.w)));
        mx = fmaxf(mx, fmaxf(fmaxf(v.x, v.y), fmaxf(v.z, v.w)));
    }
    float wmin, wmax;
    blk_minmax(mn, mx, &wmin, &wmax);
    float range = wmax - wmin;

    int i4 = lb * 256 + tid;
    float4 v4 = ((const float4*)w)[i4];
    float4 l4 = ((const float4*)lap)[i4];
    float vv[4] = {v4.x, v4.y, v4.z, v4.w};
    float ll[4] = {l4.x, l4.y, l4.z, l4.w};
    float fo[4];
    float ef = 0.f, el = 0.f, spl = 0.f;
    #pragma unroll
    for (int k = 0; k < 4; ++k) {
        float v = vv[k];
        float tt = (v - wmin) / range;            // same FP sequence as ref
        int idx = (int)floorf(tt * 100.0f);
        float val = (idx < 100) ? v * aff[idx] : 0.0f;
        fo[k] = val;
        float e = expf(ll[k]);
        ef += expf(val);
        el += e;
        spl += e * (ll[k] - val);
    }
    ((float4*)f)[i4] = make_float4(fo[0], fo[1], fo[2], fo[3]);
    float sef  = blk_sum(ef);
    float sel  = blk_sum(el);
    float sspl = blk_sum(spl);
    if (tid == 0) {
        g_s.kp_ef[t * 40 + lb]  = sef;
        g_s.kp_el[t * 40 + lb]  = sel;
        g_s.kp_spl[t * 40 + lb] = sspl;
    }
}

// ---------------- 1x1 adder: 32px x 8og (og=warp), 4 outs/thread -----------
// 4 accumulators: 2 outputs-pairs x even/odd channel (chain-splitting).
// FUSED: blockIdx.y<8 -> ds (stats), else c1 (no stats).
template<int CIN, bool FUSED, bool BN_IN, bool STATS_T>
__global__ void __launch_bounds__(256) adder1x1_kernel(
    const float* __restrict__ in, const float* __restrict__ wsrc_a,
    float* __restrict__ out_a, int Cout_a,
    const double* __restrict__ bsum, const double* __restrict__ bss,
    const float* __restrict__ bg, const float* __restrict__ bb,
    double* __restrict__ osum_a, double* __restrict__ oss_a)
{
    __shared__ __align__(16) ULL wq[16 * CIN];   // [og][c][pr(2)]
    __shared__ float scale[CIN], shift[CIN];
    int tid = threadIdx.x;
    int b = blockIdx.z, yb = blockIdx.y;

    const float* wsrc; float* out; int Cout, o0; bool do_stats;
    double *osum, *oss;
    if (FUSED) {
        bool is_ds = yb < 8;
        wsrc = is_ds ? g_s.f_ds : g_s.f_c1;
        out  = is_ds ? g_s.buf_ds : g_s.buf_c1;
        Cout = is_ds ? 256 : 64;
        o0   = (is_ds ? yb : yb - 8) * 32;
        do_stats = is_ds;
        osum = g_s.accd; oss = g_s.accd + 256;
    } else {
        wsrc = wsrc_a; out = out_a; Cout = Cout_a; o0 = yb * 32;
        do_stats = STATS_T; osum = osum_a; oss = oss_a;
    }
    int p0 = blockIdx.x * 32;

    for (int j = tid; j < 16 * CIN; j += 256) {
        int og = j / (2 * CIN), r = j - og * 2 * CIN;
        int c = r >> 1, pr = r & 1;
        int o = o0 + og * 4 + 2 * pr;
        wq[j] = packAB(-wsrc[o * CIN + c], -wsrc[(o + 1) * CIN + c]);
    }
    if (BN_IN) {
        if (tid < CIN) {
            double m = bsum[tid] * (1.0 / 3136.0);
            double var = bss[tid] * (1.0 / 3136.0) - m * m;
            float istd = rsqrtf((float)var + 1e-5f);
            float sc = istd * bg[tid];
            scale[tid] = sc;
            shift[tid] = bb[tid] - (float)m * sc;
        }
    }
    __syncthreads();

    int px = tid & 31, og = tid >> 5;       // og == warp id -> LDS broadcast
    int p = p0 + px;
    bool valid = p < HW;
    int pc = valid ? p : (HW - 1);

    const float* xp = in + (size_t)b * CIN * HW + pc;
    const ULL* wp = wq + og * 2 * CIN;
    ULL a0e = 0, a1e = 0, a0o = 0, a1o = 0;   // 4 independent chains

    #pragma unroll 2
    for (int c = 0; c < CIN; c += 2) {
        float xv0 = xp[(size_t)c * HW];
        float xv1 = xp[(size_t)(c + 1) * HW];
        if (BN_IN) {
            xv0 = fmaxf(fmaf(xv0, scale[c],     shift[c]),     0.0f);
            xv1 = fmaxf(fmaf(xv1, scale[c + 1], shift[c + 1]), 0.0f);
        }
        ULL xx0 = pack2(xv0), xx1 = pack2(xv1);
        ulonglong2 we = *(const ulonglong2*)(wp + c * 2);
        ulonglong2 wo = *(const ulonglong2*)(wp + c * 2 + 2);
        a0e = addf2(a0e, addf2(xx0, we.x) & ABS2_MASK);
        a1e = addf2(a1e, addf2(xx0, we.y) & ABS2_MASK);
        a0o = addf2(a0o, addf2(xx1, wo.x) & ABS2_MASK);
        a1o = addf2(a1o, addf2(xx1, wo.y) & ABS2_MASK);
    }
    ULL acc0 = addf2(a0e, a0o);
    ULL acc1 = addf2(a1e, a1o);

    float a[4];
    a[0] = __uint_as_float((unsigned)acc0); a[1] = __uint_as_float((unsigned)(acc0 >> 32));
    a[2] = __uint_as_float((unsigned)acc1); a[3] = __uint_as_float((unsigned)(acc1 >> 32));
    int ob = o0 + og * 4;
    if (valid) {
        #pragma unroll
        for (int k = 0; k < 4; ++k)
            out[((size_t)b * Cout + ob + k) * HW + p] = -a[k];
    }
    if (do_stats) {
        #pragma unroll
        for (int k = 0; k < 4; ++k) {
            float s  = valid ? -a[k] : 0.0f;
            float s2 = valid ? a[k] * a[k] : 0.0f;
            #pragma unroll
            for (int o = 16; o > 0; o >>= 1) {
                s  += __shfl_xor_sync(0xffffffffu, s,  o);
                s2 += __shfl_xor_sync(0xffffffffu, s2, o);
            }
            if (px == 0) {
                atomicAdd(&osum[ob + k], (double)s);
                atomicAdd(&oss[ob + k],  (double)s2);
            }
        }
    }
}

// ---------------- PEG depthwise 3x3: smem plane staging + bn1 stats --------
__global__ void __launch_bounds__(256) peg_stage_kernel(
    const float* __restrict__ in, const float* __restrict__ pw,
    float* __restrict__ out, double* __restrict__ osum, double* __restrict__ oss)
{
    __shared__ __align__(16) float plane[NPIX / 4];   // 784 floats
    int tid = threadIdx.x;
    int b = blockIdx.x >> 6, ch = blockIdx.x & 63;
    const float* ip = in + ((size_t)(b * 64 + ch)) * HW;
    float* op = out + ((size_t)(b * 64 + ch)) * HW;

    if (tid < 196) ((float4*)plane)[tid] = ((const float4*)ip)[tid];
    __syncthreads();

    float wc[9];
    #pragma unroll
    for (int t = 0; t < 9; ++t) wc[t] = pw[ch * 9 + t];

    float s = 0.f, s2 = 0.f;
    #pragma unroll
    for (int r = 0; r < 4; ++r) {
        int p = tid + r * 256;
        if (p < HW) {
            int y = p / 28, xx = p - y * 28;
            float acc = 0.f;
            #pragma unroll
            for (int t = 0; t < 9; ++t) {
                int yy = y + t / 3 - 1, xc = xx + t % 3 - 1;
                float v = (yy >= 0 && yy < 28 && xc >= 0 && xc < 28)
                          ? plane[yy * 28 + xc] : 0.0f;
                acc += fabsf(v - wc[t]);
            }
            op[p] = -acc;
            s += -acc;
            s2 += acc * acc;
        }
    }
    s = blk_sum(s); s2 = blk_sum(s2);
    if (tid == 0) {
        atomicAdd(&osum[ch], (double)s);
        atomicAdd(&oss[ch],  (double)s2);
    }
}

// ---------------- 3x3 adder: 2 adjacent px/thread, vector LDS --------------
// block: 128 thr = 4 og x 1 warp; each warp = 1 output pair over 28 px-pairs
// (2 rows x 14 pairs; lanes 28..31 idle). grid (14, 8, 4) = 448.
// smem tile: 64 ch x 4 rows x 32 cols padded; weights padded to 10 ULL/ch.
__global__ void __launch_bounds__(128) adder3x3_kernel(
    const float* __restrict__ in, const float* __restrict__ wsrc,
    const double* __restrict__ bsum, const double* __restrict__ bss,
    const float* __restrict__ bg, const float* __restrict__ bb,
    float* __restrict__ out,
    double* __restrict__ osum, double* __restrict__ oss)
{
    __shared__ __align__(16) float inb[64 * 128];   // 32 KB
    __shared__ __align__(16) ULL wq[4 * 640];       // 20 KB (10 ULL per ch)
    __shared__ float scale[64], shift[64];
    int tid = threadIdx.x;
    int b = blockIdx.z, o0 = blockIdx.y * 8, y0 = blockIdx.x * 2;

    if (tid < 64) {
        double m = bsum[tid] * (1.0 / 3136.0);
        double var = bss[tid] * (1.0 / 3136.0) - m * m;
        float istd = rsqrtf((float)var + 1e-5f);
        float sc = istd * bg[tid];
        scale[tid] = sc;
        shift[tid] = bb[tid] - (float)m * sc;
    }
    for (int j = tid; j < 2560; j += 128) {
        int og = j / 640, r = j - og * 640;
        int c = r / 10, t = r - c * 10;
        int o = o0 + og * 2;
        wq[j] = (t < 9)
            ? packAB(-wsrc[o * 576 + c * 9 + t], -wsrc[(o + 1) * 576 + c * 9 + t])
            : 0ULL;
    }
    __syncthreads();

    // stage padded tile: j = c<<7 | r<<5 | s; bn1+relu applied once per pixel
    for (int j = tid; j < 8192; j += 128) {
        int c = j >> 7, r = (j >> 5) & 3, sgn = j & 31;
        int sy = y0 - 1 + r, ox = sgn - 1;
        float v = 0.0f;
        if (sy >= 0 && sy < 28 && ox >= 0 && ox < 28) {
            float raw = in[((size_t)(b * 64 + c)) * HW + sy * 28 + ox];
            v = fmaxf(fmaf(raw, scale[c], shift[c]), 0.0f);
        }
        inb[j] = v;
    }
    __syncthreads();

    int lane = tid & 31, og = tid >> 5;      // og 0..3 == warp -> matches wq
    bool valid = lane < 28;
    int ln = valid ? lane : 0;
    int yl = ln / 14, pairx = ln - yl * 14;
    int x = pairx * 2;                       // even -> float2 loads aligned

    const float* tb = inb + yl * 32 + x;     // tile col s = x + dx (dx 0..3)
    const ULL* wp = wq + og * 640;
    ULL accP = 0, accQ = 0;                  // pixel x, pixel x+1

    for (int c = 0; c < 64; ++c) {
        const float* rp = tb + c * 128;
        const ULL* wc = wp + c * 10;
        ulonglong2 w01 = *(const ulonglong2*)(wc);
        ulonglong2 w23 = *(const ulonglong2*)(wc + 2);
        ulonglong2 w45 = *(const ulonglong2*)(wc + 4);
        ulonglong2 w67 = *(const ulonglong2*)(wc + 6);
        ULL w8 = wc[8];
        ULL wv[9] = {w01.x, w01.y, w23.x, w23.y, w45.x, w45.y, w67.x, w67.y, w8};
        #pragma unroll
        for (int dy = 0; dy < 3; ++dy) {
            float2 t01 = *(const float2*)(rp + dy * 32);
            float2 t23 = *(const float2*)(rp + dy * 32 + 2);
            ULL p0 = pack2(t01.x), p1 = pack2(t01.y);
            ULL p2 = pack2(t23.x), p3 = pack2(t23.y);
            ULL wa  = wv[dy * 3 + 0];
            ULL wbb = wv[dy * 3 + 1];
            ULL wcc = wv[dy * 3 + 2];
            accP = addf2(accP, addf2(p0, wa)  & ABS2_MASK);
            accP = addf2(accP, addf2(p1, wbb) & ABS2_MASK);
            accP = addf2(accP, addf2(p2, wcc) & ABS2_MASK);
            accQ = addf2(accQ, addf2(p1, wa)  & ABS2_MASK);
            accQ = addf2(accQ, addf2(p2, wbb) & ABS2_MASK);
            accQ = addf2(accQ, addf2(p3, wcc) & ABS2_MASK);
        }
    }

    float aP0 = __uint_as_float((unsigned)accP);
    float aP1 = __uint_as_float((unsigned)(accP >> 32));
    float aQ0 = __uint_as_float((unsigned)accQ);
    float aQ1 = __uint_as_float((unsigned)(accQ >> 32));
    int ob = o0 + og * 2;
    int py = (y0 + yl) * 28 + x;             // even -> float2 store aligned
    if (valid) {
        *(float2*)(out + ((size_t)b * 64 + ob) * HW + py)     = make_float2(-aP0, -aQ0);
        *(float2*)(out + ((size_t)b * 64 + ob + 1) * HW + py) = make_float2(-aP1, -aQ1);
    }
    {
        float s0 = valid ? (-aP0 - aQ0) : 0.0f;
        float q0 = valid ? (aP0 * aP0 + aQ0 * aQ0) : 0.0f;
        float s1 = valid ? (-aP1 - aQ1) : 0.0f;
        float q1 = valid ? (aP1 * aP1 + aQ1 * aQ1) : 0.0f;
        #pragma unroll
        for (int o = 16; o > 0; o >>= 1) {
            s0 += __shfl_xor_sync(0xffffffffu, s0, o);
            q0 += __shfl_xor_sync(0xffffffffu, q0, o);
            s1 += __shfl_xor_sync(0xffffffffu, s1, o);
            q1 += __shfl_xor_sync(0xffffffffu, q1, o);
        }
        if (lane == 0) {
            atomicAdd(&osum[ob],     (double)s0);
            atomicAdd(&oss[ob],      (double)q0);
            atomicAdd(&osum[ob + 1], (double)s1);
            atomicAdd(&oss[ob + 1],  (double)q1);
        }
    }
}

// ---------------- final: bn3/bnds (smem LUT) + residual + relu + KL --------
__global__ void __launch_bounds__(256) final_kernel(
    const float* __restrict__ g3, const float* __restrict__ b3,
    const float* __restrict__ gds, const float* __restrict__ bds,
    float* __restrict__ out, int out_size)
{
    __shared__ float4 lut3[3], lutd[3];   // {sc3,sh3}/{scd,shd} per plane
    int B = blockIdx.x, tid = threadIdx.x;
    int p_lo = (B * 256) / 196;           // first plane touched by this block

    if (tid < 3) {
        int plane = p_lo + tid;
        if (plane < 1024) {
            int ch = plane & 255;
            double m3d = g_s.accd[640 + ch] * (1.0 / 3136.0);
            double v3d = g_s.accd[896 + ch] * (1.0 / 3136.0) - m3d * m3d;
            float m3 = (float)m3d, istd3 = rsqrtf((float)v3d + 1e-5f);
            float sc3 = istd3 * g3[ch];
            double mdd = g_s.accd[0 + ch] * (1.0 / 3136.0);
            double vdd = g_s.accd[256 + ch] * (1.0 / 3136.0) - mdd * mdd;
            float md = (float)mdd, istdd = rsqrtf((float)vdd + 1e-5f);
            float scd = istdd * gds[ch];
            lut3[tid] = make_float4(sc3, b3[ch] - m3 * sc3, 0.f, 0.f);
            lutd[tid] = make_float4(scd, bds[ch] - md * scd, 0.f, 0.f);
        }
    }
    __syncthreads();

    int idx4 = B * 256 + tid;
    if (idx4 == 0 && out_size > 802816) {
        const float ns[4] = {32768.f, 8192.f, 36864.f, 16384.f};
        const int nb[4] = {32, 8, 36, 16};
        float kl = 0.f;
        #pragma unroll
        for (int t = 0; t < 4; ++t) {
            float ef = 0.f, el = 0.f, spl = 0.f;
            for (int lb = 0; lb < nb[t]; ++lb) {
                ef  += g_s.kp_ef[t * 40 + lb];
                el  += g_s.kp_el[t * 40 + lb];
                spl += g_s.kp_spl[t * 40 + lb];
            }
            kl += (spl / el + logf(ef) - logf(el)) / ns[t];
        }
        out[802816] = kl;
    }

    int plane = idx4 / 196;
    int li = plane - p_lo;
    float4 L3 = lut3[li], Ld = lutd[li];
    float sc3 = L3.x, sh3 = L3.y, scd = Ld.x, shd = Ld.y;

    size_t base = (size_t)idx4 * 4;
    float4 a = *(const float4*)(g_s.buf_c3 + base);
    float4 d = *(const float4*)(g_s.buf_ds + base);
    float4 o;
    o.x = fmaxf(fmaf(a.x, sc3, sh3) + fmaxf(fmaf(d.x, scd, shd), 0.f), 0.f);
    o.y = fmaxf(fmaf(a.y, sc3, sh3) + fmaxf(fmaf(d.y, scd, shd), 0.f), 0.f);
    o.z = fmaxf(fmaf(a.z, sc3, sh3) + fmaxf(fmaf(d.z, scd, shd), 0.f), 0.f);
    o.w = fmaxf(fmaf(a.w, sc3, sh3) + fmaxf(fmaf(d.w, scd, shd), 0.f), 0.f);
    *(float4*)(out + base) = o;
}

// ---------------------------------------------------------------------------
extern "C" void kernel_launch(void* const* d_in, const int* in_sizes, int n_in,
                              void* d_out, int out_size)
{
    const float* x    = (const float*)d_in[0];
    const float* w_ds = (const float*)d_in[1];
    const float* w_c1 = (const float*)d_in[2];
    const float* w_c2 = (const float*)d_in[3];
    const float* w_c3 = (const float*)d_in[4];
    const float* a_ds = (const float*)d_in[5];
    const float* a_c1 = (const float*)d_in[6];
    const float* a_c2 = (const float*)d_in[7];
    const float* a_c3 = (const float*)d_in[8];
    const float* pegw = (const float*)d_in[9];
    const float* g1   = (const float*)d_in[10];
    const float* b1   = (const float*)d_in[11];
    const float* g2   = (const float*)d_in[12];
    const float* b2   = (const float*)d_in[13];
    const float* g3   = (const float*)d_in[14];
    const float* b3   = (const float*)d_in[15];
    const float* gds  = (const float*)d_in[16];
    const float* bds  = (const float*)d_in[17];
    const float* lds  = (const float*)d_in[18];
    const float* lc1  = (const float*)d_in[19];
    const float* lc2  = (const float*)d_in[20];
    const float* lc3  = (const float*)d_in[21];
    float* out = (float*)d_out;

    Scratch* s = nullptr;
    cudaGetSymbolAddress((void**)&s, g_s);

    // 1) recon: zero accd + redundant minmax + reconstruct + KL partials
    recon_kernel<<<92, 256>>>(w_ds, w_c1, w_c2, w_c3,
                              a_ds, a_c1, a_c2, a_c3,
                              lds, lc1, lc2, lc3);

    // 2) fused ds (y<8, +bnds stats) and c1 (y=8..9) over x — 1000 blocks
    adder1x1_kernel<128, true, false, false><<<dim3(25, 10, 4), 256>>>(
        x, nullptr, nullptr, 0,
        nullptr, nullptr, nullptr, nullptr, nullptr, nullptr);

    // 3) PEG depthwise (smem plane staging, 256 blocks) + bn1 stats
    peg_stage_kernel<<<256, 256>>>(s->buf_c1, pegw, s->buf_peg,
                                   s->accd + 1152, s->accd + 1216);

    // 4) conv2 3x3: 2px/thread, vector LDS, 4 og x 1 warp (+bn2 stats)
    adder3x3_kernel<<<dim3(14, 8, 4), 128>>>(
        s->buf_peg, s->f_c2,
        s->accd + 1152, s->accd + 1216, g1, b1,
        s->buf_c2, s->accd + 512, s->accd + 576);

    // 5) conv3 1x1 with inline bn2+relu on input (+ bn3 stats) — 800 blocks
    adder1x1_kernel<64, false, true, true><<<dim3(25, 8, 4), 256>>>(
        s->buf_c2, s->f_c3, s->buf_c3, 256,
        s->accd + 512, s->accd + 576, g2, b2, s->accd + 640, s->accd + 896);

    // 6) fused epilogue: bn3 + relu(bnds) residual + relu, and KL scalar
    final_kernel<<<784, 256>>>(g3, b3, gds, bds, out, out_size);
}

// round 17
// speedup vs baseline: 1.0533x; 1.0533x over previous
#include <cuda_runtime.h>
#include <cuda_bf16.h>

typedef unsigned long long ULL;

#define HW 784
#define NPIX 3136

// ---------------------------------------------------------------------------
// accd layout (doubles): ds_sum@0, ds_ss@256, bn2_sum@512, bn2_ss@576,
// bn3_sum@640, bn3_ss@896, bn1_sum@1152, bn1_ss@1216.
// KL partial slots: kp_*[t*40 + lb]  (blocks per tensor: 32/8/36/16).
// ---------------------------------------------------------------------------
struct __align__(16) Scratch {
    float f_ds[32768], f_c1[8192], f_c2[36864], f_c3[16384];
    float kp_ef[160], kp_el[160], kp_spl[160];
    double accd[1280];
    float buf_ds[802816], buf_c3[802816];
    float buf_c1[200704], buf_peg[200704], buf_c2[200704];
};
__device__ Scratch g_s;

// ---------------- helpers --------------------------------------------------
__device__ __forceinline__ ULL addf2(ULL a, ULL b) {
    ULL r; asm("add.rn.f32x2 %0,%1,%2;" : "=l"(r) : "l"(a), "l"(b)); return r;
}
__device__ __forceinline__ ULL pack2(float v) {
    ULL r; unsigned u = __float_as_uint(v);
    asm("mov.b64 %0,{%1,%1};" : "=l"(r) : "r"(u)); return r;
}
__device__ __forceinline__ ULL packAB(float a, float b) {
    return ((ULL)__float_as_uint(b) << 32) | (ULL)__float_as_uint(a);
}
#define ABS2_MASK 0x7FFFFFFF7FFFFFFFULL

__device__ __forceinline__ float blk_sum(float v) {
    __shared__ float red[8];
    #pragma unroll
    for (int o = 16; o > 0; o >>= 1) v += __shfl_xor_sync(0xffffffffu, v, o);
    int w = threadIdx.x >> 5, l = threadIdx.x & 31;
    if (l == 0) red[w] = v;
    __syncthreads();
    if (w == 0) {
        float s = (l < 8) ? red[l] : 0.f;
        #pragma unroll
        for (int o = 4; o > 0; o >>= 1) s += __shfl_xor_sync(0xffffffffu, s, o);
        if (l == 0) red[0] = s;
    }
    __syncthreads();
    float r = red[0]; __syncthreads();
    return r;
}
__device__ __forceinline__ void blk_minmax(float mn, float mx, float* omn, float* omx) {
    __shared__ float rmn[8], rmx[8];
    #pragma unroll
    for (int o = 16; o > 0; o >>= 1) {
        mn = fminf(mn, __shfl_xor_sync(0xffffffffu, mn, o));
        mx = fmaxf(mx, __shfl_xor_sync(0xffffffffu, mx, o));
    }
    int w = threadIdx.x >> 5, l = threadIdx.x & 31;
    if (l == 0) { rmn[w] = mn; rmx[w] = mx; }
    __syncthreads();
    if (w == 0) {
        float a = (l < 8) ? rmn[l] : 3.4e38f;
        float b = (l < 8) ? rmx[l] : -3.4e38f;
        #pragma unroll
        for (int o = 4; o > 0; o >>= 1) {
            a = fminf(a, __shfl_xor_sync(0xffffffffu, a, o));
            b = fmaxf(b, __shfl_xor_sync(0xffffffffu, b, o));
        }
        if (l == 0) { rmn[0] = a; rmx[0] = b; }
    }
    __syncthreads();
    *omn = rmn[0]; *omx = rmx[0];
    __syncthreads();
}

// ---------------- recon: zero accd + per-tensor minmax + recon + KL parts --
__global__ void __launch_bounds__(256) recon_kernel(
    const float* __restrict__ w0, const float* __restrict__ w1,
    const float* __restrict__ w2, const float* __restrict__ w3,
    const float* __restrict__ a0, const float* __restrict__ a1,
    const float* __restrict__ a2, const float* __restrict__ a3,
    const float* __restrict__ l0, const float* __restrict__ l1,
    const float* __restrict__ l2, const float* __restrict__ l3)
{
    int bid = blockIdx.x, tid = threadIdx.x;
    if (bid == 0) {
        #pragma unroll
        for (int i = 0; i < 5; ++i) g_s.accd[i * 256 + tid] = 0.0;
    }
    int t, lb;
    if (bid < 32)      { t = 0; lb = bid; }
    else if (bid < 40) { t = 1; lb = bid - 32; }
    else if (bid < 76) { t = 2; lb = bid - 40; }
    else               { t = 3; lb = bid - 76; }
    const float *w, *aff, *lap; float* f; int n4;
    if (t == 0)      { w = w0; aff = a0; lap = l0; f = g_s.f_ds; n4 = 8192; }
    else if (t == 1) { w = w1; aff = a1; lap = l1; f = g_s.f_c1; n4 = 2048; }
    else if (t == 2) { w = w2; aff = a2; lap = l2; f = g_s.f_c2; n4 = 9216; }
    else             { w = w3; aff = a3; lap = l3; f = g_s.f_c3; n4 = 4096; }

    float mn = 3.4e38f, mx = -3.4e38f;
    for (int i = tid; i < n4; i += 256) {
        float4 v = ((const float4*)w)[i];
        mn = fminf(mn, fminf(fminf(v.x, v.y), fminf(v.z, v.w)));
        mx = fmaxf(mx, fmaxf(fmaxf(v.x, v.y), fmaxf(v.z, v.w)));
    }
    float wmin, wmax;
    blk_minmax(mn, mx, &wmin, &wmax);
    float range = wmax - wmin;

    int i4 = lb * 256 + tid;
    float4 v4 = ((const float4*)w)[i4];
    float4 l4 = ((const float4*)lap)[i4];
    float vv[4] = {v4.x, v4.y, v4.z, v4.w};
    float ll[4] = {l4.x, l4.y, l4.z, l4.w};
    float fo[4];
    float ef = 0.f, el = 0.f, spl = 0.f;
    #pragma unroll
    for (int k = 0; k < 4; ++k) {
        float v = vv[k];
        float tt = (v - wmin) / range;            // same FP sequence as ref
        int idx = (int)floorf(tt * 100.0f);
        float val = (idx < 100) ? v * aff[idx] : 0.0f;
        fo[k] = val;
        float e = expf(ll[k]);
        ef += expf(val);
        el += e;
        spl += e * (ll[k] - val);
    }
    ((float4*)f)[i4] = make_float4(fo[0], fo[1], fo[2], fo[3]);
    float sef  = blk_sum(ef);
    float sel  = blk_sum(el);
    float sspl = blk_sum(spl);
    if (tid == 0) {
        g_s.kp_ef[t * 40 + lb]  = sef;
        g_s.kp_el[t * 40 + lb]  = sel;
        g_s.kp_spl[t * 40 + lb] = sspl;
    }
}

// ---------------- 1x1 adder: 32px x 8og (og=warp), 4 outs/thread -----------
// 4 accumulators: 2 outputs-pairs x even/odd channel (chain-splitting).
// FUSED: blockIdx.y<8 -> ds (stats), else c1 (no stats).
template<int CIN, bool FUSED, bool BN_IN, bool STATS_T>
__global__ void __launch_bounds__(256) adder1x1_kernel(
    const float* __restrict__ in, const float* __restrict__ wsrc_a,
    float* __restrict__ out_a, int Cout_a,
    const double* __restrict__ bsum, const double* __restrict__ bss,
    const float* __restrict__ bg, const float* __restrict__ bb,
    double* __restrict__ osum_a, double* __restrict__ oss_a)
{
    __shared__ __align__(16) ULL wq[16 * CIN];   // [og][c][pr(2)]
    __shared__ float scale[CIN], shift[CIN];
    int tid = threadIdx.x;
    int b = blockIdx.z, yb = blockIdx.y;

    const float* wsrc; float* out; int Cout, o0; bool do_stats;
    double *osum, *oss;
    if (FUSED) {
        bool is_ds = yb < 8;
        wsrc = is_ds ? g_s.f_ds : g_s.f_c1;
        out  = is_ds ? g_s.buf_ds : g_s.buf_c1;
        Cout = is_ds ? 256 : 64;
        o0   = (is_ds ? yb : yb - 8) * 32;
        do_stats = is_ds;
        osum = g_s.accd; oss = g_s.accd + 256;
    } else {
        wsrc = wsrc_a; out = out_a; Cout = Cout_a; o0 = yb * 32;
        do_stats = STATS_T; osum = osum_a; oss = oss_a;
    }
    int p0 = blockIdx.x * 32;

    for (int j = tid; j < 16 * CIN; j += 256) {
        int og = j / (2 * CIN), r = j - og * 2 * CIN;
        int c = r >> 1, pr = r & 1;
        int o = o0 + og * 4 + 2 * pr;
        wq[j] = packAB(-wsrc[o * CIN + c], -wsrc[(o + 1) * CIN + c]);
    }
    if (BN_IN) {
        if (tid < CIN) {
            double m = bsum[tid] * (1.0 / 3136.0);
            double var = bss[tid] * (1.0 / 3136.0) - m * m;
            float istd = rsqrtf((float)var + 1e-5f);
            float sc = istd * bg[tid];
            scale[tid] = sc;
            shift[tid] = bb[tid] - (float)m * sc;
        }
    }
    __syncthreads();

    int px = tid & 31, og = tid >> 5;       // og == warp id -> LDS broadcast
    int p = p0 + px;
    bool valid = p < HW;
    int pc = valid ? p : (HW - 1);

    const float* xp = in + (size_t)b * CIN * HW + pc;
    const ULL* wp = wq + og * 2 * CIN;
    ULL a0e = 0, a1e = 0, a0o = 0, a1o = 0;   // 4 independent chains

    #pragma unroll 2
    for (int c = 0; c < CIN; c += 2) {
        float xv0 = xp[(size_t)c * HW];
        float xv1 = xp[(size_t)(c + 1) * HW];
        if (BN_IN) {
            xv0 = fmaxf(fmaf(xv0, scale[c],     shift[c]),     0.0f);
            xv1 = fmaxf(fmaf(xv1, scale[c + 1], shift[c + 1]), 0.0f);
        }
        ULL xx0 = pack2(xv0), xx1 = pack2(xv1);
        ulonglong2 we = *(const ulonglong2*)(wp + c * 2);
        ulonglong2 wo = *(const ulonglong2*)(wp + c * 2 + 2);
        a0e = addf2(a0e, addf2(xx0, we.x) & ABS2_MASK);
        a1e = addf2(a1e, addf2(xx0, we.y) & ABS2_MASK);
        a0o = addf2(a0o, addf2(xx1, wo.x) & ABS2_MASK);
        a1o = addf2(a1o, addf2(xx1, wo.y) & ABS2_MASK);
    }
    ULL acc0 = addf2(a0e, a0o);
    ULL acc1 = addf2(a1e, a1o);

    float a[4];
    a[0] = __uint_as_float((unsigned)acc0); a[1] = __uint_as_float((unsigned)(acc0 >> 32));
    a[2] = __uint_as_float((unsigned)acc1); a[3] = __uint_as_float((unsigned)(acc1 >> 32));
    int ob = o0 + og * 4;
    if (valid) {
        #pragma unroll
        for (int k = 0; k < 4; ++k)
            out[((size_t)b * Cout + ob + k) * HW + p] = -a[k];
    }
    if (do_stats) {
        #pragma unroll
        for (int k = 0; k < 4; ++k) {
            float s  = valid ? -a[k] : 0.0f;
            float s2 = valid ? a[k] * a[k] : 0.0f;
            #pragma unroll
            for (int o = 16; o > 0; o >>= 1) {
                s  += __shfl_xor_sync(0xffffffffu, s,  o);
                s2 += __shfl_xor_sync(0xffffffffu, s2, o);
            }
            if (px == 0) {
                atomicAdd(&osum[ob + k], (double)s);
                atomicAdd(&oss[ob + k],  (double)s2);
            }
        }
    }
}

// ---------------- PEG depthwise 3x3: smem plane staging + bn1 stats --------
__global__ void __launch_bounds__(256) peg_stage_kernel(
    const float* __restrict__ in, const float* __restrict__ pw,
    float* __restrict__ out, double* __restrict__ osum, double* __restrict__ oss)
{
    __shared__ __align__(16) float plane[NPIX / 4];   // 784 floats
    int tid = threadIdx.x;
    int b = blockIdx.x >> 6, ch = blockIdx.x & 63;
    const float* ip = in + ((size_t)(b * 64 + ch)) * HW;
    float* op = out + ((size_t)(b * 64 + ch)) * HW;

    if (tid < 196) ((float4*)plane)[tid] = ((const float4*)ip)[tid];
    __syncthreads();

    float wc[9];
    #pragma unroll
    for (int t = 0; t < 9; ++t) wc[t] = pw[ch * 9 + t];

    float s = 0.f, s2 = 0.f;
    #pragma unroll
    for (int r = 0; r < 4; ++r) {
        int p = tid + r * 256;
        if (p < HW) {
            int y = p / 28, xx = p - y * 28;
            float acc = 0.f;
            #pragma unroll
            for (int t = 0; t < 9; ++t) {
                int yy = y + t / 3 - 1, xc = xx + t % 3 - 1;
                float v = (yy >= 0 && yy < 28 && xc >= 0 && xc < 28)
                          ? plane[yy * 28 + xc] : 0.0f;
                acc += fabsf(v - wc[t]);
            }
            op[p] = -acc;
            s += -acc;
            s2 += acc * acc;
        }
    }
    s = blk_sum(s); s2 = blk_sum(s2);
    if (tid == 0) {
        atomicAdd(&osum[ch], (double)s);
        atomicAdd(&oss[ch],  (double)s2);
    }
}

// ---------------- 3x3 adder: 2px/thread, channel-split warps ---------------
// block: 256 thr = 4 og x 2 half-warps; warp (og,half) does channels
// half*32..half*32+31 for output pair og. Partials combined via smem.
// grid (14, 8, 4) = 448. smem: 32KB tile + 20KB weights + 4KB partials.
__global__ void __launch_bounds__(256) adder3x3_kernel(
    const float* __restrict__ in, const float* __restrict__ wsrc,
    const double* __restrict__ bsum, const double* __restrict__ bss,
    const float* __restrict__ bg, const float* __restrict__ bb,
    float* __restrict__ out,
    double* __restrict__ osum, double* __restrict__ oss)
{
    __shared__ __align__(16) float inb[64 * 128];   // 32 KB
    __shared__ __align__(16) ULL wq[4 * 640];       // 20 KB (10 ULL per ch)
    __shared__ __align__(16) ULL partP[4][32], partQ[4][32];   // 2+2 KB
    __shared__ float scale[64], shift[64];
    int tid = threadIdx.x;
    int b = blockIdx.z, o0 = blockIdx.y * 8, y0 = blockIdx.x * 2;

    if (tid < 64) {
        double m = bsum[tid] * (1.0 / 3136.0);
        double var = bss[tid] * (1.0 / 3136.0) - m * m;
        float istd = rsqrtf((float)var + 1e-5f);
        float sc = istd * bg[tid];
        scale[tid] = sc;
        shift[tid] = bb[tid] - (float)m * sc;
    }
    for (int j = tid; j < 2560; j += 256) {
        int og = j / 640, r = j - og * 640;
        int c = r / 10, t = r - c * 10;
        int o = o0 + og * 2;
        wq[j] = (t < 9)
            ? packAB(-wsrc[o * 576 + c * 9 + t], -wsrc[(o + 1) * 576 + c * 9 + t])
            : 0ULL;
    }
    __syncthreads();

    // stage padded tile: j = c<<7 | r<<5 | s; bn1+relu applied once per pixel
    for (int j = tid; j < 8192; j += 256) {
        int c = j >> 7, r = (j >> 5) & 3, sgn = j & 31;
        int sy = y0 - 1 + r, ox = sgn - 1;
        float v = 0.0f;
        if (sy >= 0 && sy < 28 && ox >= 0 && ox < 28) {
            float raw = in[((size_t)(b * 64 + c)) * HW + sy * 28 + ox];
            v = fmaxf(fmaf(raw, scale[c], shift[c]), 0.0f);
        }
        inb[j] = v;
    }
    __syncthreads();

    int lane = tid & 31;
    int wid = tid >> 5;                      // 0..7
    int og = wid >> 1, half = wid & 1;       // og 0..3, channel half 0..1
    bool valid = lane < 28;
    int ln = valid ? lane : 0;
    int yl = ln / 14, pairx = ln - yl * 14;
    int x = pairx * 2;                       // even -> float2 loads aligned

    const float* tb = inb + yl * 32 + x + half * 32 * 128;  // ch base half*32
    const ULL* wp = wq + og * 640 + half * 32 * 10;
    ULL accP = 0, accQ = 0;                  // pixel x, pixel x+1

    for (int c = 0; c < 32; ++c) {
        const float* rp = tb + c * 128;
        const ULL* wc = wp + c * 10;
        ulonglong2 w01 = *(const ulonglong2*)(wc);
        ulonglong2 w23 = *(const ulonglong2*)(wc + 2);
        ulonglong2 w45 = *(const ulonglong2*)(wc + 4);
        ulonglong2 w67 = *(const ulonglong2*)(wc + 6);
        ULL w8 = wc[8];
        ULL wv[9] = {w01.x, w01.y, w23.x, w23.y, w45.x, w45.y, w67.x, w67.y, w8};
        #pragma unroll
        for (int dy = 0; dy < 3; ++dy) {
            float2 t01 = *(const float2*)(rp + dy * 32);
            float2 t23 = *(const float2*)(rp + dy * 32 + 2);
            ULL p0 = pack2(t01.x), p1 = pack2(t01.y);
            ULL p2 = pack2(t23.x), p3 = pack2(t23.y);
            ULL wa  = wv[dy * 3 + 0];
            ULL wbb = wv[dy * 3 + 1];
            ULL wcc = wv[dy * 3 + 2];
            accP = addf2(accP, addf2(p0, wa)  & ABS2_MASK);
            accP = addf2(accP, addf2(p1, wbb) & ABS2_MASK);
            accP = addf2(accP, addf2(p2, wcc) & ABS2_MASK);
            accQ = addf2(accQ, addf2(p1, wa)  & ABS2_MASK);
            accQ = addf2(accQ, addf2(p2, wbb) & ABS2_MASK);
            accQ = addf2(accQ, addf2(p3, wcc) & ABS2_MASK);
        }
    }

    // combine halves: half=1 publishes, half=0 adds and finishes
    if (half == 1) {
        partP[og][lane] = accP;
        partQ[og][lane] = accQ;
    }
    __syncthreads();
    if (half == 0) {
        accP = addf2(accP, partP[og][lane]);
        accQ = addf2(accQ, partQ[og][lane]);

        float aP0 = __uint_as_float((unsigned)accP);
        float aP1 = __uint_as_float((unsigned)(accP >> 32));
        float aQ0 = __uint_as_float((unsigned)accQ);
        float aQ1 = __uint_as_float((unsigned)(accQ >> 32));
        int ob = o0 + og * 2;
        int py = (y0 + yl) * 28 + x;         // even -> float2 store aligned
        if (valid) {
            *(float2*)(out + ((size_t)b * 64 + ob) * HW + py)     = make_float2(-aP0, -aQ0);
            *(float2*)(out + ((size_t)b * 64 + ob + 1) * HW + py) = make_float2(-aP1, -aQ1);
        }
        float s0 = valid ? (-aP0 - aQ0) : 0.0f;
        float q0 = valid ? (aP0 * aP0 + aQ0 * aQ0) : 0.0f;
        float s1 = valid ? (-aP1 - aQ1) : 0.0f;
        float q1 = valid ? (aP1 * aP1 + aQ1 * aQ1) : 0.0f;
        #pragma unroll
        for (int o = 16; o > 0; o >>= 1) {
            s0 += __shfl_xor_sync(0xffffffffu, s0, o);
            q0 += __shfl_xor_sync(0xffffffffu, q0, o);
            s1 += __shfl_xor_sync(0xffffffffu, s1, o);
            q1 += __shfl_xor_sync(0xffffffffu, q1, o);
        }
        if (lane == 0) {
            atomicAdd(&osum[ob],     (double)s0);
            atomicAdd(&oss[ob],      (double)q0);
            atomicAdd(&osum[ob + 1], (double)s1);
            atomicAdd(&oss[ob + 1],  (double)q1);
        }
    }
}

// ---------------- final: bn3/bnds (smem LUT) + residual + relu + KL --------
__global__ void __launch_bounds__(256) final_kernel(
    const float* __restrict__ g3, const float* __restrict__ b3,
    const float* __restrict__ gds, const float* __restrict__ bds,
    float* __restrict__ out, int out_size)
{
    __shared__ float4 lut3[3], lutd[3];   // {sc3,sh3}/{scd,shd} per plane
    int B = blockIdx.x, tid = threadIdx.x;
    int p_lo = (B * 256) / 196;           // first plane touched by this block

    if (tid < 3) {
        int plane = p_lo + tid;
        if (plane < 1024) {
            int ch = plane & 255;
            double m3d = g_s.accd[640 + ch] * (1.0 / 3136.0);
            double v3d = g_s.accd[896 + ch] * (1.0 / 3136.0) - m3d * m3d;
            float m3 = (float)m3d, istd3 = rsqrtf((float)v3d + 1e-5f);
            float sc3 = istd3 * g3[ch];
            double mdd = g_s.accd[0 + ch] * (1.0 / 3136.0);
            double vdd = g_s.accd[256 + ch] * (1.0 / 3136.0) - mdd * mdd;
            float md = (float)mdd, istdd = rsqrtf((float)vdd + 1e-5f);
            float scd = istdd * gds[ch];
            lut3[tid] = make_float4(sc3, b3[ch] - m3 * sc3, 0.f, 0.f);
            lutd[tid] = make_float4(scd, bds[ch] - md * scd, 0.f, 0.f);
        }
    }
    __syncthreads();

    int idx4 = B * 256 + tid;
    if (idx4 == 0 && out_size > 802816) {
        const float ns[4] = {32768.f, 8192.f, 36864.f, 16384.f};
        const int nb[4] = {32, 8, 36, 16};
        float kl = 0.f;
        #pragma unroll
        for (int t = 0; t < 4; ++t) {
            float ef = 0.f, el = 0.f, spl = 0.f;
            for (int lb = 0; lb < nb[t]; ++lb) {
                ef  += g_s.kp_ef[t * 40 + lb];
                el  += g_s.kp_el[t * 40 + lb];
                spl += g_s.kp_spl[t * 40 + lb];
            }
            kl += (spl / el + logf(ef) - logf(el)) / ns[t];
        }
        out[802816] = kl;
    }

    int plane = idx4 / 196;
    int li = plane - p_lo;
    float4 L3 = lut3[li], Ld = lutd[li];
    float sc3 = L3.x, sh3 = L3.y, scd = Ld.x, shd = Ld.y;

    size_t base = (size_t)idx4 * 4;
    float4 a = *(const float4*)(g_s.buf_c3 + base);
    float4 d = *(const float4*)(g_s.buf_ds + base);
    float4 o;
    o.x = fmaxf(fmaf(a.x, sc3, sh3) + fmaxf(fmaf(d.x, scd, shd), 0.f), 0.f);
    o.y = fmaxf(fmaf(a.y, sc3, sh3) + fmaxf(fmaf(d.y, scd, shd), 0.f), 0.f);
    o.z = fmaxf(fmaf(a.z, sc3, sh3) + fmaxf(fmaf(d.z, scd, shd), 0.f), 0.f);
    o.w = fmaxf(fmaf(a.w, sc3, sh3) + fmaxf(fmaf(d.w, scd, shd), 0.f), 0.f);
    *(float4*)(out + base) = o;
}

// ---------------------------------------------------------------------------
extern "C" void kernel_launch(void* const* d_in, const int* in_sizes, int n_in,
                              void* d_out, int out_size)
{
    const float* x    = (const float*)d_in[0];
    const float* w_ds = (const float*)d_in[1];
    const float* w_c1 = (const float*)d_in[2];
    const float* w_c2 = (const float*)d_in[3];
    const float* w_c3 = (const float*)d_in[4];
    const float* a_ds = (const float*)d_in[5];
    const float* a_c1 = (const float*)d_in[6];
    const float* a_c2 = (const float*)d_in[7];
    const float* a_c3 = (const float*)d_in[8];
    const float* pegw = (const float*)d_in[9];
    const float* g1   = (const float*)d_in[10];
    const float* b1   = (const float*)d_in[11];
    const float* g2   = (const float*)d_in[12];
    const float* b2   = (const float*)d_in[13];
    const float* g3   = (const float*)d_in[14];
    const float* b3   = (const float*)d_in[15];
    const float* gds  = (const float*)d_in[16];
    const float* bds  = (const float*)d_in[17];
    const float* lds  = (const float*)d_in[18];
    const float* lc1  = (const float*)d_in[19];
    const float* lc2  = (const float*)d_in[20];
    const float* lc3  = (const float*)d_in[21];
    float* out = (float*)d_out;

    Scratch* s = nullptr;
    cudaGetSymbolAddress((void**)&s, g_s);

    // 1) recon: zero accd + redundant minmax + reconstruct + KL partials
    recon_kernel<<<92, 256>>>(w_ds, w_c1, w_c2, w_c3,
                              a_ds, a_c1, a_c2, a_c3,
                              lds, lc1, lc2, lc3);

    // 2) fused ds (y<8, +bnds stats) and c1 (y=8..9) over x — 1000 blocks
    adder1x1_kernel<128, true, false, false><<<dim3(25, 10, 4), 256>>>(
        x, nullptr, nullptr, 0,
        nullptr, nullptr, nullptr, nullptr, nullptr, nullptr);

    // 3) PEG depthwise (smem plane staging, 256 blocks) + bn1 stats
    peg_stage_kernel<<<256, 256>>>(s->buf_c1, pegw, s->buf_peg,
                                   s->accd + 1152, s->accd + 1216);

    // 4) conv2 3x3: 2px/thread, channel-split warps (+bn2 stats)
    adder3x3_kernel<<<dim3(14, 8, 4), 256>>>(
        s->buf_peg, s->f_c2,
        s->accd + 1152, s->accd + 1216, g1, b1,
        s->buf_c2, s->accd + 512, s->accd + 576);

    // 5) conv3 1x1 with inline bn2+relu on input (+ bn3 stats) — 800 blocks
    adder1x1_kernel<64, false, true, true><<<dim3(25, 8, 4), 256>>>(
        s->buf_c2, s->f_c3, s->buf_c3, 256,
        s->accd + 512, s->accd + 576, g2, b2, s->accd + 640, s->accd + 896);

    // 6) fused epilogue: bn3 + relu(bnds) residual + relu, and KL scalar
    final_kernel<<<784, 256>>>(g3, b3, gds, bds, out, out_size);
}